// round 11
// baseline (speedup 1.0000x reference)
#include <cuda_runtime.h>
#include <cuda_bf16.h>
#include <cstdint>

#define H 40
#define T 256
#define BATCH 8192
#define EPB 64
#define THREADS 256
#define NBLOCKS (BATCH / EPB)   // 128

#define PITCH 88                // bf16 cols per element row (h1 0..39 | h2 40..79 | x 80..82 | pad)
#define NFRAG 160               // L1: 3kt x 20nt ; L2: 5kt x 20nt
#define OFF_BF 0
#define BF_BYTES (NFRAG * 32 * 16)          // 81920
#define OFF_HSHI BF_BYTES
#define HS_BYTES (2 * EPB * PITCH * 2)      // 22528 (2 buffers)
#define OFF_HSLO (OFF_HSHI + HS_BYTES)      // 104448
#define OFF_B1S  (OFF_HSLO + HS_BYTES)      // 126976 : float[160]
#define OFF_B2S  (OFF_B1S + 640)            // 127616
#define SMEM_BYTES (OFF_B2S + 640)          // 128256

__device__ __forceinline__ float tanhfast(float x) {
    float y; asm("tanh.approx.f32 %0, %1;" : "=f"(y) : "f"(x)); return y;
}
__device__ __forceinline__ float sigf(float x) {
    return fmaf(0.5f, tanhfast(0.5f * x), 0.5f);
}
__device__ __forceinline__ void bsplit(float v, __nv_bfloat16 &hi, __nv_bfloat16 &lo) {
    hi = __float2bfloat16(v);
    lo = __float2bfloat16(v - __bfloat162float(hi));
}
__device__ __forceinline__ uint32_t packb(__nv_bfloat16 a, __nv_bfloat16 b) {
    __nv_bfloat162 t; t.x = a; t.y = b;
    return *(uint32_t*)&t;
}
__device__ __forceinline__ void mma16816(float* d, const uint32_t* a, uint32_t b0, uint32_t b1) {
    asm("mma.sync.aligned.m16n8k16.row.col.f32.bf16.bf16.f32 "
        "{%0,%1,%2,%3},{%4,%5,%6,%7},{%8,%9},{%0,%1,%2,%3};"
        : "+f"(d[0]), "+f"(d[1]), "+f"(d[2]), "+f"(d[3])
        : "r"(a[0]), "r"(a[1]), "r"(a[2]), "r"(a[3]), "r"(b0), "r"(b1));
}

__global__ __launch_bounds__(THREADS, 1)
void lstm2_tc2_kernel(const float* __restrict__ x,
                      const float* __restrict__ W_ih1,
                      const float* __restrict__ W_hh1,
                      const float* __restrict__ b1,
                      const float* __restrict__ W_ih2,
                      const float* __restrict__ W_hh2,
                      const float* __restrict__ b2,
                      const float* __restrict__ W_fc,
                      const float* __restrict__ b_fc,
                      float* __restrict__ out)
{
    extern __shared__ char smem[];
    uint4* __restrict__ BF = (uint4*)(smem + OFF_BF);
    __nv_bfloat16* __restrict__ HShi = (__nv_bfloat16*)(smem + OFF_HSHI);
    __nv_bfloat16* __restrict__ HSlo = (__nv_bfloat16*)(smem + OFF_HSLO);
    float* __restrict__ B1S = (float*)(smem + OFF_B1S);
    float* __restrict__ B2S = (float*)(smem + OFF_B2S);

    const int tid  = threadIdx.x;
    const int w    = tid >> 5;
    const int lane = tid & 31;
    const int gid  = lane >> 2;     // 0..7
    const int tig  = lane & 3;      // 0..3
    const int mg   = w >> 2;        // 0..1 : owns m-tiles {2mg, 2mg+1}
    const int ng   = w & 3;         // 0..3 : owns n-tiles ng*5 .. ng*5+4

    const float* xp = x + ((long)blockIdx.x * EPB + (tid & 63)) * (T * 3);

    // ---------------- init: zero both HS buffers; bias tables ----------------
    for (int i = tid; i < 2 * EPB * PITCH; i += THREADS) {
        HShi[i] = __float2bfloat16(0.0f);
        HSlo[i] = __float2bfloat16(0.0f);
    }
    for (int n = tid; n < 160; n += THREADS) {
        int r = (n & 3) * H + (n >> 2);
        B1S[n] = __ldg(b1 + r);
        B2S[n] = __ldg(b2 + r);
    }
    // ---------------- init: pack B fragments ----------------
    for (int f = w; f < NFRAG; f += 8) {
        int layer, kt, nt;
        if (f < 60) { layer = 0; kt = f / 20; nt = f % 20; }
        else        { layer = 1; kt = (f - 60) / 20; nt = (f - 60) % 20; }
        int n = nt * 8 + gid;
        int r = (n & 3) * H + (n >> 2);
        float v[4];
        #pragma unroll
        for (int q = 0; q < 4; q++) {
            int k = kt * 16 + 2 * tig + ((q >> 1) * 8) + (q & 1);
            float val;
            if (layer == 0) {
                if (k < 40)      val = W_hh1[r * H + k];
                else if (k < 43) val = W_ih1[r * 3 + (k - 40)];
                else             val = 0.0f;        // bias folded into D-init
            } else {
                if (k < 40)      val = W_ih2[r * H + k];
                else             val = W_hh2[r * H + (k - 40)];   // k <= 79
            }
            v[q] = val;
        }
        __nv_bfloat16 h0, l0, h1v, l1, h2v, l2, h3, l3;
        bsplit(v[0], h0, l0); bsplit(v[1], h1v, l1);
        bsplit(v[2], h2v, l2); bsplit(v[3], h3, l3);
        uint4 pk;
        pk.x = packb(h0, h1v);
        pk.y = packb(h2v, h3);
        pk.z = packb(l0, l1);
        pk.w = packb(l2, l3);
        BF[f * 32 + lane] = pk;
    }
    __syncthreads();
    // stage x(0) -> buf0, x(1) -> buf1
    if (tid < EPB) {
        __nv_bfloat16 hh, hl;
        #pragma unroll
        for (int bu = 0; bu < 2; bu++) {
            #pragma unroll
            for (int c = 0; c < 3; c++) {
                bsplit(__ldg(xp + bu * 3 + c), hh, hl);
                HShi[bu * EPB * PITCH + tid * PITCH + 80 + c] = hh;
                HSlo[bu * EPB * PITCH + tid * PITCH + 80 + c] = hl;
            }
        }
    }
    __syncthreads();

    // ---------------- recurrent state ----------------
    float cs1[2][5][2], cs2[2][5][2];   // [mi][ntl][row e0/e1]
    #pragma unroll
    for (int mi = 0; mi < 2; mi++)
        #pragma unroll
        for (int i = 0; i < 5; i++) {
            cs1[mi][i][0] = cs1[mi][i][1] = 0.0f;
            cs2[mi][i][0] = cs2[mi][i][1] = 0.0f;
        }

    const int nbase = (ng * 5) * 8 + 2 * tig;

    // epilogue helper
    auto epi = [&](float D[2][5][4], float cs[2][5][2],
                   __nv_bfloat16* Whi, __nv_bfloat16* Wlo, int colbase) {
        #pragma unroll
        for (int mi = 0; mi < 2; mi++) {
            const int e0 = (mg * 2 + mi) * 16 + gid;
            const int e1 = e0 + 8;
            #pragma unroll
            for (int ntl = 0; ntl < 5; ntl++) {
                float u0, v0, u1, v1;
                if ((tig & 1) == 0) {
                    u0 = sigf(D[mi][ntl][0]); v0 = sigf(D[mi][ntl][1]);
                    u1 = sigf(D[mi][ntl][2]); v1 = sigf(D[mi][ntl][3]);
                } else {
                    u0 = tanhfast(D[mi][ntl][0]); v0 = sigf(D[mi][ntl][1]);
                    u1 = tanhfast(D[mi][ntl][2]); v1 = sigf(D[mi][ntl][3]);
                }
                float g0 = __shfl_xor_sync(0xffffffffu, u0, 1);
                float g1 = __shfl_xor_sync(0xffffffffu, u1, 1);
                cs[mi][ntl][0] = fmaf(v0, cs[mi][ntl][0], u0 * g0);
                cs[mi][ntl][1] = fmaf(v1, cs[mi][ntl][1], u1 * g1);
                float tc0 = tanhfast(cs[mi][ntl][0]);
                float tc1 = tanhfast(cs[mi][ntl][1]);
                float r0 = __shfl_xor_sync(0xffffffffu, tc0, 1);
                float r1 = __shfl_xor_sync(0xffffffffu, tc1, 1);
                if (tig & 1) {
                    int unit = 2 * (ng * 5 + ntl) + (tig >> 1);
                    float hv0 = v0 * r0;
                    float hv1 = v1 * r1;
                    __nv_bfloat16 hh, hl;
                    bsplit(hv0, hh, hl);
                    Whi[e0 * PITCH + colbase + unit] = hh;
                    Wlo[e0 * PITCH + colbase + unit] = hl;
                    bsplit(hv1, hh, hl);
                    Whi[e1 * PITCH + colbase + unit] = hh;
                    Wlo[e1 * PITCH + colbase + unit] = hl;
                }
            }
        }
    };

    for (int t = 0; t < T; t++) {
        const int p = t & 1;
        __nv_bfloat16* Phi = HShi + p * EPB * PITCH;         // buf[p]   (this step's writes; x(t))
        __nv_bfloat16* Plo = HSlo + p * EPB * PITCH;
        __nv_bfloat16* Qhi = HShi + (1 - p) * EPB * PITCH;   // buf[1-p] (h1(t-1), h2(t-1))
        __nv_bfloat16* Qlo = HSlo + (1 - p) * EPB * PITCH;

        // global prefetch of x(t+2)
        float xr0 = 0.f, xr1 = 0.f, xr2 = 0.f;
        if (tid < EPB) {
            int tn = (t + 2 < T) ? (t + 2) : (T - 1);
            xr0 = __ldg(xp + tn * 3 + 0);
            xr1 = __ldg(xp + tn * 3 + 1);
            xr2 = __ldg(xp + tn * 3 + 2);
        }

        float D[2][5][4];

        // ================= P1: L1 MMA  (A = [h1(t-1) | x(t)]) =================
        #pragma unroll
        for (int ntl = 0; ntl < 5; ntl++) {
            float bb0 = B1S[nbase + ntl * 8];
            float bb1 = B1S[nbase + ntl * 8 + 1];
            #pragma unroll
            for (int mi = 0; mi < 2; mi++) {
                D[mi][ntl][0] = bb0; D[mi][ntl][1] = bb1;
                D[mi][ntl][2] = bb0; D[mi][ntl][3] = bb1;
            }
        }
        #pragma unroll
        for (int kt = 0; kt < 3; kt++) {
            uint32_t ah[2][4], al[2][4];
            const int c0 = (kt < 2) ? kt * 16 + 2 * tig : 32 + 2 * tig;
            const int c8 = (kt < 2) ? kt * 16 + 8 + 2 * tig : 80 + 2 * tig;
            const __nv_bfloat16* s8hi = (kt < 2) ? Qhi : Phi;   // x(t) lives in buf[p]
            const __nv_bfloat16* s8lo = (kt < 2) ? Qlo : Plo;
            #pragma unroll
            for (int mi = 0; mi < 2; mi++) {
                const int e0 = (mg * 2 + mi) * 16 + gid;
                const int e1 = e0 + 8;
                ah[mi][0] = *(const uint32_t*)(Qhi + e0 * PITCH + c0);
                ah[mi][1] = *(const uint32_t*)(Qhi + e1 * PITCH + c0);
                ah[mi][2] = *(const uint32_t*)(s8hi + e0 * PITCH + c8);
                ah[mi][3] = *(const uint32_t*)(s8hi + e1 * PITCH + c8);
                al[mi][0] = *(const uint32_t*)(Qlo + e0 * PITCH + c0);
                al[mi][1] = *(const uint32_t*)(Qlo + e1 * PITCH + c0);
                al[mi][2] = *(const uint32_t*)(s8lo + e0 * PITCH + c8);
                al[mi][3] = *(const uint32_t*)(s8lo + e1 * PITCH + c8);
            }
            #pragma unroll
            for (int ntl = 0; ntl < 5; ntl++) {
                uint4 bb = BF[(kt * 20 + ng * 5 + ntl) * 32 + lane];
                #pragma unroll
                for (int mi = 0; mi < 2; mi++) {
                    mma16816(D[mi][ntl], ah[mi], bb.x, bb.y);
                    mma16816(D[mi][ntl], al[mi], bb.x, bb.y);
                    mma16816(D[mi][ntl], ah[mi], bb.z, bb.w);
                }
            }
        }
        // epi1: write h1(t) -> buf[p] cols 0..39
        epi(D, cs1, Phi, Plo, 0);
        __syncthreads();

        // stage x(t+2) -> buf[p] cols 80..82 (readers of old x(t) finished pre-BAR)
        if (tid < EPB) {
            __nv_bfloat16 hh, hl;
            bsplit(xr0, hh, hl); Phi[tid * PITCH + 80] = hh; Plo[tid * PITCH + 80] = hl;
            bsplit(xr1, hh, hl); Phi[tid * PITCH + 81] = hh; Plo[tid * PITCH + 81] = hl;
            bsplit(xr2, hh, hl); Phi[tid * PITCH + 82] = hh; Plo[tid * PITCH + 82] = hl;
        }

        // ================= P3: L2 MMA  (A = [h1(t) | h2(t-1)]) =================
        #pragma unroll
        for (int ntl = 0; ntl < 5; ntl++) {
            float bb0 = B2S[nbase + ntl * 8];
            float bb1 = B2S[nbase + ntl * 8 + 1];
            #pragma unroll
            for (int mi = 0; mi < 2; mi++) {
                D[mi][ntl][0] = bb0; D[mi][ntl][1] = bb1;
                D[mi][ntl][2] = bb0; D[mi][ntl][3] = bb1;
            }
        }
        #pragma unroll
        for (int kt = 0; kt < 5; kt++) {
            uint32_t ah[2][4], al[2][4];
            const int c0 = kt * 16 + 2 * tig;
            const int c8 = kt * 16 + 8 + 2 * tig;
            // cols < 40 = h1(t) -> buf[p]; cols >= 40 = h2(t-1) -> buf[1-p]
            const __nv_bfloat16* s0hi = (kt < 2) ? Phi : ((kt == 2) ? Phi : Qhi);
            const __nv_bfloat16* s0lo = (kt < 2) ? Plo : ((kt == 2) ? Plo : Qlo);
            const __nv_bfloat16* s8hi = (kt < 2) ? Phi : Qhi;
            const __nv_bfloat16* s8lo = (kt < 2) ? Plo : Qlo;
            #pragma unroll
            for (int mi = 0; mi < 2; mi++) {
                const int e0 = (mg * 2 + mi) * 16 + gid;
                const int e1 = e0 + 8;
                ah[mi][0] = *(const uint32_t*)(s0hi + e0 * PITCH + c0);
                ah[mi][1] = *(const uint32_t*)(s0hi + e1 * PITCH + c0);
                ah[mi][2] = *(const uint32_t*)(s8hi + e0 * PITCH + c8);
                ah[mi][3] = *(const uint32_t*)(s8hi + e1 * PITCH + c8);
                al[mi][0] = *(const uint32_t*)(s0lo + e0 * PITCH + c0);
                al[mi][1] = *(const uint32_t*)(s0lo + e1 * PITCH + c0);
                al[mi][2] = *(const uint32_t*)(s8lo + e0 * PITCH + c8);
                al[mi][3] = *(const uint32_t*)(s8lo + e1 * PITCH + c8);
            }
            #pragma unroll
            for (int ntl = 0; ntl < 5; ntl++) {
                uint4 bb = BF[((60 + kt * 20) + ng * 5 + ntl) * 32 + lane];
                #pragma unroll
                for (int mi = 0; mi < 2; mi++) {
                    mma16816(D[mi][ntl], ah[mi], bb.x, bb.y);
                    mma16816(D[mi][ntl], al[mi], bb.x, bb.y);
                    mma16816(D[mi][ntl], ah[mi], bb.z, bb.w);
                }
            }
        }
        // epi2: write h2(t) -> buf[p] cols 40..79  (no barrier: next readers cross >=1 BAR)
        epi(D, cs2, Phi, Plo, 40);
    }
    __syncthreads();

    // ---------------- FC epilogue (h2(T-1) in buf[(T-1)&1] = buf1) ----------------
    if (tid < 2 * EPB) {
        int e = tid >> 1, q = tid & 1;
        const __nv_bfloat16* Fhi = HShi + 1 * EPB * PITCH;
        const __nv_bfloat16* Flo = HSlo + 1 * EPB * PITCH;
        float acc = __ldg(b_fc + q);
        #pragma unroll 8
        for (int u = 0; u < H; u++) {
            float hval = __bfloat162float(Fhi[e * PITCH + 40 + u])
                       + __bfloat162float(Flo[e * PITCH + 40 + u]);
            acc = fmaf(hval, __ldg(W_fc + q * H + u), acc);
        }
        out[((long)blockIdx.x * EPB + e) * 2 + q] = acc;
    }
}

extern "C" void kernel_launch(void* const* d_in, const int* in_sizes, int n_in,
                              void* d_out, int out_size)
{
    const float* x     = (const float*)d_in[0];
    const float* W_ih1 = (const float*)d_in[1];
    const float* W_hh1 = (const float*)d_in[2];
    const float* b1    = (const float*)d_in[3];
    const float* W_ih2 = (const float*)d_in[4];
    const float* W_hh2 = (const float*)d_in[5];
    const float* b2    = (const float*)d_in[6];
    const float* W_fc  = (const float*)d_in[7];
    const float* b_fc  = (const float*)d_in[8];
    float* out = (float*)d_out;

    cudaFuncSetAttribute(lstm2_tc2_kernel,
                         cudaFuncAttributeMaxDynamicSharedMemorySize, SMEM_BYTES);

    lstm2_tc2_kernel<<<NBLOCKS, THREADS, SMEM_BYTES>>>(
        x, W_ih1, W_hh1, b1, W_ih2, W_hh2, b2, W_fc, b_fc, out);
}

// round 12
// speedup vs baseline: 1.2730x; 1.2730x over previous
#include <cuda_runtime.h>
#include <cuda_bf16.h>
#include <cstdint>

#define H 40
#define T 256
#define BATCH 8192
#define EPB 32
#define THREADS 256
#define NBLOCKS (BATCH / EPB)   // 256

#define PITCH 88                // bf16 cols per element row (h1 0..39 | h2 40..79 | x 80..82 | pad)
#define NFRAG 160               // L1: 3kt x 20nt ; L2: 5kt x 20nt
#define OFF_BF 0
#define BF_BYTES (NFRAG * 32 * 16)          // 81920
#define OFF_HSHI BF_BYTES
#define HS_BYTES (2 * EPB * PITCH * 2)      // 11264 (2 buffers)
#define OFF_HSLO (OFF_HSHI + HS_BYTES)
#define OFF_B1S  (OFF_HSLO + HS_BYTES)      // float[160]
#define OFF_B2S  (OFF_B1S + 640)
#define SMEM_BYTES (OFF_B2S + 640)          // 105728 -> 2 CTAs/SM

__device__ __forceinline__ float tanhfast(float x) {
    float y; asm("tanh.approx.f32 %0, %1;" : "=f"(y) : "f"(x)); return y;
}
__device__ __forceinline__ float sigf(float x) {
    return fmaf(0.5f, tanhfast(0.5f * x), 0.5f);
}
__device__ __forceinline__ void bsplit(float v, __nv_bfloat16 &hi, __nv_bfloat16 &lo) {
    hi = __float2bfloat16(v);
    lo = __float2bfloat16(v - __bfloat162float(hi));
}
__device__ __forceinline__ uint32_t packb(__nv_bfloat16 a, __nv_bfloat16 b) {
    __nv_bfloat162 t; t.x = a; t.y = b;
    return *(uint32_t*)&t;
}
__device__ __forceinline__ void mma16816(float* d, const uint32_t* a, uint32_t b0, uint32_t b1) {
    asm("mma.sync.aligned.m16n8k16.row.col.f32.bf16.bf16.f32 "
        "{%0,%1,%2,%3},{%4,%5,%6,%7},{%8,%9},{%0,%1,%2,%3};"
        : "+f"(d[0]), "+f"(d[1]), "+f"(d[2]), "+f"(d[3])
        : "r"(a[0]), "r"(a[1]), "r"(a[2]), "r"(a[3]), "r"(b0), "r"(b1));
}

__global__ __launch_bounds__(THREADS, 2)
void lstm2_tc3_kernel(const float* __restrict__ x,
                      const float* __restrict__ W_ih1,
                      const float* __restrict__ W_hh1,
                      const float* __restrict__ b1,
                      const float* __restrict__ W_ih2,
                      const float* __restrict__ W_hh2,
                      const float* __restrict__ b2,
                      const float* __restrict__ W_fc,
                      const float* __restrict__ b_fc,
                      float* __restrict__ out)
{
    extern __shared__ char smem[];
    uint4* __restrict__ BF = (uint4*)(smem + OFF_BF);
    __nv_bfloat16* __restrict__ HShi = (__nv_bfloat16*)(smem + OFF_HSHI);
    __nv_bfloat16* __restrict__ HSlo = (__nv_bfloat16*)(smem + OFF_HSLO);
    float* __restrict__ B1S = (float*)(smem + OFF_B1S);
    float* __restrict__ B2S = (float*)(smem + OFF_B2S);

    const int tid  = threadIdx.x;
    const int w    = tid >> 5;
    const int lane = tid & 31;
    const int gid  = lane >> 2;     // 0..7
    const int tig  = lane & 3;      // 0..3
    const int mt   = w >> 2;        // 0..1 : m-tile (16 elements)
    const int ng   = w & 3;         // 0..3 : n-tiles ng*5 .. ng*5+4

    const float* xp = x + ((long)blockIdx.x * EPB + (tid & 31)) * (T * 3);

    // ---------------- init: zero both HS buffers; bias tables ----------------
    for (int i = tid; i < 2 * EPB * PITCH; i += THREADS) {
        HShi[i] = __float2bfloat16(0.0f);
        HSlo[i] = __float2bfloat16(0.0f);
    }
    for (int n = tid; n < 160; n += THREADS) {
        int r = (n & 3) * H + (n >> 2);
        B1S[n] = __ldg(b1 + r);
        B2S[n] = __ldg(b2 + r);
    }
    // ---------------- init: pack B fragments ----------------
    for (int f = w; f < NFRAG; f += 8) {
        int layer, kt, nt;
        if (f < 60) { layer = 0; kt = f / 20; nt = f % 20; }
        else        { layer = 1; kt = (f - 60) / 20; nt = (f - 60) % 20; }
        int n = nt * 8 + gid;
        int r = (n & 3) * H + (n >> 2);   // PyTorch row = gate*H + unit
        float v[4];
        #pragma unroll
        for (int q = 0; q < 4; q++) {
            int k = kt * 16 + 2 * tig + ((q >> 1) * 8) + (q & 1);
            float val;
            if (layer == 0) {
                if (k < 40)      val = W_hh1[r * H + k];
                else if (k < 43) val = W_ih1[r * 3 + (k - 40)];
                else             val = 0.0f;          // bias folded into D-init
            } else {
                if (k < 40)      val = W_ih2[r * H + k];
                else             val = W_hh2[r * H + (k - 40)];
            }
            v[q] = val;
        }
        __nv_bfloat16 h0, l0, h1v, l1, h2v, l2, h3, l3;
        bsplit(v[0], h0, l0); bsplit(v[1], h1v, l1);
        bsplit(v[2], h2v, l2); bsplit(v[3], h3, l3);
        uint4 pk;
        pk.x = packb(h0, h1v);
        pk.y = packb(h2v, h3);
        pk.z = packb(l0, l1);
        pk.w = packb(l2, l3);
        BF[f * 32 + lane] = pk;
    }
    __syncthreads();
    // stage x(0) -> buf0, x(1) -> buf1
    if (tid < EPB) {
        __nv_bfloat16 hh, hl;
        #pragma unroll
        for (int bu = 0; bu < 2; bu++) {
            #pragma unroll
            for (int c = 0; c < 3; c++) {
                bsplit(__ldg(xp + bu * 3 + c), hh, hl);
                HShi[bu * EPB * PITCH + tid * PITCH + 80 + c] = hh;
                HSlo[bu * EPB * PITCH + tid * PITCH + 80 + c] = hl;
            }
        }
    }
    __syncthreads();

    // ---------------- recurrent state ----------------
    float cs1[5][2], cs2[5][2];
    #pragma unroll
    for (int i = 0; i < 5; i++) {
        cs1[i][0] = cs1[i][1] = 0.0f;
        cs2[i][0] = cs2[i][1] = 0.0f;
    }

    const int e0 = mt * 16 + gid;
    const int e1 = e0 + 8;
    const int nbase = (ng * 5) * 8 + 2 * tig;

    auto epi = [&](float D[5][4], float cs[5][2],
                   __nv_bfloat16* Whi, __nv_bfloat16* Wlo, int colbase) {
        #pragma unroll
        for (int ntl = 0; ntl < 5; ntl++) {
            float u0, v0, u1, v1;
            if ((tig & 1) == 0) {
                u0 = sigf(D[ntl][0]); v0 = sigf(D[ntl][1]);
                u1 = sigf(D[ntl][2]); v1 = sigf(D[ntl][3]);
            } else {
                u0 = tanhfast(D[ntl][0]); v0 = sigf(D[ntl][1]);
                u1 = tanhfast(D[ntl][2]); v1 = sigf(D[ntl][3]);
            }
            float g0 = __shfl_xor_sync(0xffffffffu, u0, 1);
            float g1 = __shfl_xor_sync(0xffffffffu, u1, 1);
            cs[ntl][0] = fmaf(v0, cs[ntl][0], u0 * g0);
            cs[ntl][1] = fmaf(v1, cs[ntl][1], u1 * g1);
            float tc0 = tanhfast(cs[ntl][0]);
            float tc1 = tanhfast(cs[ntl][1]);
            float r0 = __shfl_xor_sync(0xffffffffu, tc0, 1);
            float r1 = __shfl_xor_sync(0xffffffffu, tc1, 1);
            if (tig & 1) {
                int unit = 2 * (ng * 5 + ntl) + (tig >> 1);
                float hv0 = v0 * r0;
                float hv1 = v1 * r1;
                __nv_bfloat16 hh, hl;
                bsplit(hv0, hh, hl);
                Whi[e0 * PITCH + colbase + unit] = hh;
                Wlo[e0 * PITCH + colbase + unit] = hl;
                bsplit(hv1, hh, hl);
                Whi[e1 * PITCH + colbase + unit] = hh;
                Wlo[e1 * PITCH + colbase + unit] = hl;
            }
        }
    };

    for (int t = 0; t < T; t++) {
        const int p = t & 1;
        __nv_bfloat16* Phi = HShi + p * EPB * PITCH;         // buf[p]: this step's writes, x(t)
        __nv_bfloat16* Plo = HSlo + p * EPB * PITCH;
        __nv_bfloat16* Qhi = HShi + (1 - p) * EPB * PITCH;   // buf[1-p]: h1(t-1), h2(t-1)
        __nv_bfloat16* Qlo = HSlo + (1 - p) * EPB * PITCH;

        // global prefetch of x(t+2)
        float xr0 = 0.f, xr1 = 0.f, xr2 = 0.f;
        if (tid < EPB) {
            int tn = (t + 2 < T) ? (t + 2) : (T - 1);
            xr0 = __ldg(xp + tn * 3 + 0);
            xr1 = __ldg(xp + tn * 3 + 1);
            xr2 = __ldg(xp + tn * 3 + 2);
        }

        float D[5][4];

        // ================= P1: L1 MMA  (A = [h1(t-1) | x(t)]) =================
        #pragma unroll
        for (int ntl = 0; ntl < 5; ntl++) {
            float bb0 = B1S[nbase + ntl * 8];
            float bb1 = B1S[nbase + ntl * 8 + 1];
            D[ntl][0] = bb0; D[ntl][1] = bb1;
            D[ntl][2] = bb0; D[ntl][3] = bb1;
        }
        #pragma unroll
        for (int kt = 0; kt < 3; kt++) {
            const int c0 = (kt < 2) ? kt * 16 + 2 * tig : 32 + 2 * tig;
            const int c8 = (kt < 2) ? kt * 16 + 8 + 2 * tig : 80 + 2 * tig;
            const __nv_bfloat16* s8hi = (kt < 2) ? Qhi : Phi;   // x(t) lives in buf[p]
            const __nv_bfloat16* s8lo = (kt < 2) ? Qlo : Plo;
            uint32_t ah[4], al[4];
            ah[0] = *(const uint32_t*)(Qhi + e0 * PITCH + c0);
            ah[1] = *(const uint32_t*)(Qhi + e1 * PITCH + c0);
            ah[2] = *(const uint32_t*)(s8hi + e0 * PITCH + c8);
            ah[3] = *(const uint32_t*)(s8hi + e1 * PITCH + c8);
            al[0] = *(const uint32_t*)(Qlo + e0 * PITCH + c0);
            al[1] = *(const uint32_t*)(Qlo + e1 * PITCH + c0);
            al[2] = *(const uint32_t*)(s8lo + e0 * PITCH + c8);
            al[3] = *(const uint32_t*)(s8lo + e1 * PITCH + c8);
            #pragma unroll
            for (int ntl = 0; ntl < 5; ntl++) {
                uint4 bb = BF[(kt * 20 + ng * 5 + ntl) * 32 + lane];
                mma16816(D[ntl], ah, bb.x, bb.y);
                mma16816(D[ntl], al, bb.x, bb.y);
                mma16816(D[ntl], ah, bb.z, bb.w);
            }
        }
        // epi1: write h1(t) -> buf[p] cols 0..39
        epi(D, cs1, Phi, Plo, 0);
        __syncthreads();

        // stage x(t+2) -> buf[p] cols 80..82 (x(t) readers finished pre-BAR)
        if (tid < EPB) {
            __nv_bfloat16 hh, hl;
            bsplit(xr0, hh, hl); Phi[tid * PITCH + 80] = hh; Plo[tid * PITCH + 80] = hl;
            bsplit(xr1, hh, hl); Phi[tid * PITCH + 81] = hh; Plo[tid * PITCH + 81] = hl;
            bsplit(xr2, hh, hl); Phi[tid * PITCH + 82] = hh; Plo[tid * PITCH + 82] = hl;
        }

        // ================= P3: L2 MMA  (A = [h1(t) | h2(t-1)]) =================
        #pragma unroll
        for (int ntl = 0; ntl < 5; ntl++) {
            float bb0 = B2S[nbase + ntl * 8];
            float bb1 = B2S[nbase + ntl * 8 + 1];
            D[ntl][0] = bb0; D[ntl][1] = bb1;
            D[ntl][2] = bb0; D[ntl][3] = bb1;
        }
        #pragma unroll
        for (int kt = 0; kt < 5; kt++) {
            const int c0 = kt * 16 + 2 * tig;
            const int c8 = kt * 16 + 8 + 2 * tig;
            // cols < 40 = h1(t) in buf[p]; cols >= 40 = h2(t-1) in buf[1-p]
            const __nv_bfloat16* s0hi = (kt <= 2) ? Phi : Qhi;
            const __nv_bfloat16* s0lo = (kt <= 2) ? Plo : Qlo;
            const __nv_bfloat16* s8hi = (kt < 2) ? Phi : Qhi;
            const __nv_bfloat16* s8lo = (kt < 2) ? Plo : Qlo;
            uint32_t ah[4], al[4];
            ah[0] = *(const uint32_t*)(s0hi + e0 * PITCH + c0);
            ah[1] = *(const uint32_t*)(s0hi + e1 * PITCH + c0);
            ah[2] = *(const uint32_t*)(s8hi + e0 * PITCH + c8);
            ah[3] = *(const uint32_t*)(s8hi + e1 * PITCH + c8);
            al[0] = *(const uint32_t*)(s0lo + e0 * PITCH + c0);
            al[1] = *(const uint32_t*)(s0lo + e1 * PITCH + c0);
            al[2] = *(const uint32_t*)(s8lo + e0 * PITCH + c8);
            al[3] = *(const uint32_t*)(s8lo + e1 * PITCH + c8);
            #pragma unroll
            for (int ntl = 0; ntl < 5; ntl++) {
                uint4 bb = BF[((60 + kt * 20) + ng * 5 + ntl) * 32 + lane];
                mma16816(D[ntl], ah, bb.x, bb.y);
                mma16816(D[ntl], al, bb.x, bb.y);
                mma16816(D[ntl], ah, bb.z, bb.w);
            }
        }
        // epi2: write h2(t) -> buf[p] cols 40..79 (next readers cross >=1 BAR)
        epi(D, cs2, Phi, Plo, 40);
    }
    __syncthreads();

    // ---------------- FC epilogue (h2(T-1) in buf[(T-1)&1] = buf1) ----------------
    if (tid < 2 * EPB) {
        int e = tid >> 1, q = tid & 1;
        const __nv_bfloat16* Fhi = HShi + 1 * EPB * PITCH;
        const __nv_bfloat16* Flo = HSlo + 1 * EPB * PITCH;
        float acc = __ldg(b_fc + q);
        #pragma unroll 8
        for (int u = 0; u < H; u++) {
            float hval = __bfloat162float(Fhi[e * PITCH + 40 + u])
                       + __bfloat162float(Flo[e * PITCH + 40 + u]);
            acc = fmaf(hval, __ldg(W_fc + q * H + u), acc);
        }
        out[((long)blockIdx.x * EPB + e) * 2 + q] = acc;
    }
}

extern "C" void kernel_launch(void* const* d_in, const int* in_sizes, int n_in,
                              void* d_out, int out_size)
{
    const float* x     = (const float*)d_in[0];
    const float* W_ih1 = (const float*)d_in[1];
    const float* W_hh1 = (const float*)d_in[2];
    const float* b1    = (const float*)d_in[3];
    const float* W_ih2 = (const float*)d_in[4];
    const float* W_hh2 = (const float*)d_in[5];
    const float* b2    = (const float*)d_in[6];
    const float* W_fc  = (const float*)d_in[7];
    const float* b_fc  = (const float*)d_in[8];
    float* out = (float*)d_out;

    cudaFuncSetAttribute(lstm2_tc3_kernel,
                         cudaFuncAttributeMaxDynamicSharedMemorySize, SMEM_BYTES);

    lstm2_tc3_kernel<<<NBLOCKS, THREADS, SMEM_BYTES>>>(
        x, W_ih1, W_hh1, b1, W_ih2, W_hh2, b2, W_fc, b_fc, out);
}

// round 13
// speedup vs baseline: 1.5732x; 1.2358x over previous
#include <cuda_runtime.h>
#include <cuda_fp16.h>
#include <cstdint>

#define H 40
#define T 256
#define BATCH 8192
#define EPB 32
#define THREADS 256
#define NBLOCKS (BATCH / EPB)   // 256

#define PITCH 88                // fp16 cols per element row (h1 0..39 | h2 40..79 | x 80..82 | pad)
#define NFRAG 160               // L1: 3kt x 20nt ; L2: 5kt x 20nt
#define OFF_BF 0
#define BF_BYTES (NFRAG * 32 * 8)           // 40960 (uint2 per lane: Bhi only)
#define OFF_HSHI BF_BYTES
#define HS_BYTES (2 * EPB * PITCH * 2)      // 11264 (2 buffers)
#define OFF_HSLO (OFF_HSHI + HS_BYTES)
#define OFF_B1S  (OFF_HSLO + HS_BYTES)      // float[160]
#define OFF_B2S  (OFF_B1S + 640)
#define SMEM_BYTES (OFF_B2S + 640)          // 64768 -> 2 CTAs/SM easily

__device__ __forceinline__ float tanhfast(float x) {
    float y; asm("tanh.approx.f32 %0, %1;" : "=f"(y) : "f"(x)); return y;
}
__device__ __forceinline__ float sigf(float x) {
    return fmaf(0.5f, tanhfast(0.5f * x), 0.5f);
}
__device__ __forceinline__ void hsplit(float v, __half &hi, __half &lo) {
    hi = __float2half_rn(v);
    lo = __float2half_rn(v - __half2float(hi));
}
__device__ __forceinline__ uint32_t packh(__half a, __half b) {
    __half2 t; t.x = a; t.y = b;
    return *(uint32_t*)&t;
}
__device__ __forceinline__ void mma16816h(float* d, const uint32_t* a, uint32_t b0, uint32_t b1) {
    asm("mma.sync.aligned.m16n8k16.row.col.f32.f16.f16.f32 "
        "{%0,%1,%2,%3},{%4,%5,%6,%7},{%8,%9},{%0,%1,%2,%3};"
        : "+f"(d[0]), "+f"(d[1]), "+f"(d[2]), "+f"(d[3])
        : "r"(a[0]), "r"(a[1]), "r"(a[2]), "r"(a[3]), "r"(b0), "r"(b1));
}

__global__ __launch_bounds__(THREADS, 2)
void lstm2_tc4_kernel(const float* __restrict__ x,
                      const float* __restrict__ W_ih1,
                      const float* __restrict__ W_hh1,
                      const float* __restrict__ b1,
                      const float* __restrict__ W_ih2,
                      const float* __restrict__ W_hh2,
                      const float* __restrict__ b2,
                      const float* __restrict__ W_fc,
                      const float* __restrict__ b_fc,
                      float* __restrict__ out)
{
    extern __shared__ char smem[];
    uint2* __restrict__ BF = (uint2*)(smem + OFF_BF);
    __half* __restrict__ HShi = (__half*)(smem + OFF_HSHI);
    __half* __restrict__ HSlo = (__half*)(smem + OFF_HSLO);
    float* __restrict__ B1S = (float*)(smem + OFF_B1S);
    float* __restrict__ B2S = (float*)(smem + OFF_B2S);

    const int tid  = threadIdx.x;
    const int w    = tid >> 5;
    const int lane = tid & 31;
    const int gid  = lane >> 2;     // 0..7
    const int tig  = lane & 3;      // 0..3
    const int mt   = w >> 2;        // 0..1 : m-tile (16 elements)
    const int ng   = w & 3;         // 0..3 : n-tiles ng*5 .. ng*5+4

    const float* xp = x + ((long)blockIdx.x * EPB + (tid & 31)) * (T * 3);

    // ---------------- init: zero both HS buffers; bias tables ----------------
    for (int i = tid; i < 2 * EPB * PITCH; i += THREADS) {
        HShi[i] = __float2half(0.0f);
        HSlo[i] = __float2half(0.0f);
    }
    for (int n = tid; n < 160; n += THREADS) {
        int r = (n & 3) * H + (n >> 2);
        B1S[n] = __ldg(b1 + r);
        B2S[n] = __ldg(b2 + r);
    }
    // ---------------- init: pack B fragments (fp16 hi only) ----------------
    for (int f = w; f < NFRAG; f += 8) {
        int layer, kt, nt;
        if (f < 60) { layer = 0; kt = f / 20; nt = f % 20; }
        else        { layer = 1; kt = (f - 60) / 20; nt = (f - 60) % 20; }
        int n = nt * 8 + gid;
        int r = (n & 3) * H + (n >> 2);   // PyTorch row = gate*H + unit
        float v[4];
        #pragma unroll
        for (int q = 0; q < 4; q++) {
            int k = kt * 16 + 2 * tig + ((q >> 1) * 8) + (q & 1);
            float val;
            if (layer == 0) {
                if (k < 40)      val = W_hh1[r * H + k];
                else if (k < 43) val = W_ih1[r * 3 + (k - 40)];
                else             val = 0.0f;          // bias folded into D-init
            } else {
                if (k < 40)      val = W_ih2[r * H + k];
                else             val = W_hh2[r * H + (k - 40)];
            }
            v[q] = val;
        }
        uint2 pk;
        pk.x = packh(__float2half_rn(v[0]), __float2half_rn(v[1]));
        pk.y = packh(__float2half_rn(v[2]), __float2half_rn(v[3]));
        BF[f * 32 + lane] = pk;
    }
    __syncthreads();
    // stage x(0) -> buf0, x(1) -> buf1
    if (tid < EPB) {
        __half hh, hl;
        #pragma unroll
        for (int bu = 0; bu < 2; bu++) {
            #pragma unroll
            for (int c = 0; c < 3; c++) {
                hsplit(__ldg(xp + bu * 3 + c), hh, hl);
                HShi[bu * EPB * PITCH + tid * PITCH + 80 + c] = hh;
                HSlo[bu * EPB * PITCH + tid * PITCH + 80 + c] = hl;
            }
        }
    }
    __syncthreads();

    // ---------------- recurrent state ----------------
    float cs1[5][2], cs2[5][2];
    #pragma unroll
    for (int i = 0; i < 5; i++) {
        cs1[i][0] = cs1[i][1] = 0.0f;
        cs2[i][0] = cs2[i][1] = 0.0f;
    }

    const int e0 = mt * 16 + gid;
    const int e1 = e0 + 8;
    const int nbase = (ng * 5) * 8 + 2 * tig;

    auto epi = [&](float D[5][4], float cs[5][2],
                   __half* Whi, __half* Wlo, int colbase) {
        #pragma unroll
        for (int ntl = 0; ntl < 5; ntl++) {
            float u0, v0, u1, v1;
            if ((tig & 1) == 0) {
                u0 = sigf(D[ntl][0]); v0 = sigf(D[ntl][1]);
                u1 = sigf(D[ntl][2]); v1 = sigf(D[ntl][3]);
            } else {
                u0 = tanhfast(D[ntl][0]); v0 = sigf(D[ntl][1]);
                u1 = tanhfast(D[ntl][2]); v1 = sigf(D[ntl][3]);
            }
            float g0 = __shfl_xor_sync(0xffffffffu, u0, 1);
            float g1 = __shfl_xor_sync(0xffffffffu, u1, 1);
            cs[ntl][0] = fmaf(v0, cs[ntl][0], u0 * g0);
            cs[ntl][1] = fmaf(v1, cs[ntl][1], u1 * g1);
            float tc0 = tanhfast(cs[ntl][0]);
            float tc1 = tanhfast(cs[ntl][1]);
            float r0 = __shfl_xor_sync(0xffffffffu, tc0, 1);
            float r1 = __shfl_xor_sync(0xffffffffu, tc1, 1);
            if (tig & 1) {
                int unit = 2 * (ng * 5 + ntl) + (tig >> 1);
                float hv0 = v0 * r0;
                float hv1 = v1 * r1;
                __half hh, hl;
                hsplit(hv0, hh, hl);
                Whi[e0 * PITCH + colbase + unit] = hh;
                Wlo[e0 * PITCH + colbase + unit] = hl;
                hsplit(hv1, hh, hl);
                Whi[e1 * PITCH + colbase + unit] = hh;
                Wlo[e1 * PITCH + colbase + unit] = hl;
            }
        }
    };

    for (int t = 0; t < T; t++) {
        const int p = t & 1;
        __half* Phi = HShi + p * EPB * PITCH;         // buf[p]: this step's writes, x(t)
        __half* Plo = HSlo + p * EPB * PITCH;
        __half* Qhi = HShi + (1 - p) * EPB * PITCH;   // buf[1-p]: h1(t-1), h2(t-1)
        __half* Qlo = HSlo + (1 - p) * EPB * PITCH;

        // global prefetch of x(t+2)
        float xr0 = 0.f, xr1 = 0.f, xr2 = 0.f;
        if (tid < EPB) {
            int tn = (t + 2 < T) ? (t + 2) : (T - 1);
            xr0 = __ldg(xp + tn * 3 + 0);
            xr1 = __ldg(xp + tn * 3 + 1);
            xr2 = __ldg(xp + tn * 3 + 2);
        }

        float D[5][4];

        // ================= P1: L1 MMA  (A = [h1(t-1) | x(t)]) =================
        #pragma unroll
        for (int ntl = 0; ntl < 5; ntl++) {
            float bb0 = B1S[nbase + ntl * 8];
            float bb1 = B1S[nbase + ntl * 8 + 1];
            D[ntl][0] = bb0; D[ntl][1] = bb1;
            D[ntl][2] = bb0; D[ntl][3] = bb1;
        }
        #pragma unroll
        for (int kt = 0; kt < 3; kt++) {
            const int c0 = (kt < 2) ? kt * 16 + 2 * tig : 32 + 2 * tig;
            const int c8 = (kt < 2) ? kt * 16 + 8 + 2 * tig : 80 + 2 * tig;
            const __half* s8hi = (kt < 2) ? Qhi : Phi;   // x(t) lives in buf[p]
            const __half* s8lo = (kt < 2) ? Qlo : Plo;
            uint32_t ah[4], al[4];
            ah[0] = *(const uint32_t*)(Qhi + e0 * PITCH + c0);
            ah[1] = *(const uint32_t*)(Qhi + e1 * PITCH + c0);
            ah[2] = *(const uint32_t*)(s8hi + e0 * PITCH + c8);
            ah[3] = *(const uint32_t*)(s8hi + e1 * PITCH + c8);
            al[0] = *(const uint32_t*)(Qlo + e0 * PITCH + c0);
            al[1] = *(const uint32_t*)(Qlo + e1 * PITCH + c0);
            al[2] = *(const uint32_t*)(s8lo + e0 * PITCH + c8);
            al[3] = *(const uint32_t*)(s8lo + e1 * PITCH + c8);
            #pragma unroll
            for (int ntl = 0; ntl < 5; ntl++) {
                uint2 bb = BF[(kt * 20 + ng * 5 + ntl) * 32 + lane];
                mma16816h(D[ntl], ah, bb.x, bb.y);
                mma16816h(D[ntl], al, bb.x, bb.y);
            }
        }
        // epi1: write h1(t) -> buf[p] cols 0..39
        epi(D, cs1, Phi, Plo, 0);
        __syncthreads();

        // stage x(t+2) -> buf[p] cols 80..82 (x(t) readers finished pre-BAR)
        if (tid < EPB) {
            __half hh, hl;
            hsplit(xr0, hh, hl); Phi[tid * PITCH + 80] = hh; Plo[tid * PITCH + 80] = hl;
            hsplit(xr1, hh, hl); Phi[tid * PITCH + 81] = hh; Plo[tid * PITCH + 81] = hl;
            hsplit(xr2, hh, hl); Phi[tid * PITCH + 82] = hh; Plo[tid * PITCH + 82] = hl;
        }

        // ================= P3: L2 MMA  (A = [h1(t) | h2(t-1)]) =================
        #pragma unroll
        for (int ntl = 0; ntl < 5; ntl++) {
            float bb0 = B2S[nbase + ntl * 8];
            float bb1 = B2S[nbase + ntl * 8 + 1];
            D[ntl][0] = bb0; D[ntl][1] = bb1;
            D[ntl][2] = bb0; D[ntl][3] = bb1;
        }
        #pragma unroll
        for (int kt = 0; kt < 5; kt++) {
            const int c0 = kt * 16 + 2 * tig;
            const int c8 = kt * 16 + 8 + 2 * tig;
            // cols < 40 = h1(t) in buf[p]; cols >= 40 = h2(t-1) in buf[1-p]
            const __half* s0hi = (kt <= 2) ? Phi : Qhi;
            const __half* s0lo = (kt <= 2) ? Plo : Qlo;
            const __half* s8hi = (kt < 2) ? Phi : Qhi;
            const __half* s8lo = (kt < 2) ? Plo : Qlo;
            uint32_t ah[4], al[4];
            ah[0] = *(const uint32_t*)(s0hi + e0 * PITCH + c0);
            ah[1] = *(const uint32_t*)(s0hi + e1 * PITCH + c0);
            ah[2] = *(const uint32_t*)(s8hi + e0 * PITCH + c8);
            ah[3] = *(const uint32_t*)(s8hi + e1 * PITCH + c8);
            al[0] = *(const uint32_t*)(s0lo + e0 * PITCH + c0);
            al[1] = *(const uint32_t*)(s0lo + e1 * PITCH + c0);
            al[2] = *(const uint32_t*)(s8lo + e0 * PITCH + c8);
            al[3] = *(const uint32_t*)(s8lo + e1 * PITCH + c8);
            #pragma unroll
            for (int ntl = 0; ntl < 5; ntl++) {
                uint2 bb = BF[((60 + kt * 20) + ng * 5 + ntl) * 32 + lane];
                mma16816h(D[ntl], ah, bb.x, bb.y);
                mma16816h(D[ntl], al, bb.x, bb.y);
            }
        }
        // epi2: write h2(t) -> buf[p] cols 40..79 (next readers cross >=1 BAR)
        epi(D, cs2, Phi, Plo, 40);
    }
    __syncthreads();

    // ---------------- FC epilogue (h2(T-1) in buf[(T-1)&1] = buf1) ----------------
    if (tid < 2 * EPB) {
        int e = tid >> 1, q = tid & 1;
        const __half* Fhi = HShi + 1 * EPB * PITCH;
        const __half* Flo = HSlo + 1 * EPB * PITCH;
        float acc = __ldg(b_fc + q);
        #pragma unroll 8
        for (int u = 0; u < H; u++) {
            float hval = __half2float(Fhi[e * PITCH + 40 + u])
                       + __half2float(Flo[e * PITCH + 40 + u]);
            acc = fmaf(hval, __ldg(W_fc + q * H + u), acc);
        }
        out[((long)blockIdx.x * EPB + e) * 2 + q] = acc;
    }
}

extern "C" void kernel_launch(void* const* d_in, const int* in_sizes, int n_in,
                              void* d_out, int out_size)
{
    const float* x     = (const float*)d_in[0];
    const float* W_ih1 = (const float*)d_in[1];
    const float* W_hh1 = (const float*)d_in[2];
    const float* b1    = (const float*)d_in[3];
    const float* W_ih2 = (const float*)d_in[4];
    const float* W_hh2 = (const float*)d_in[5];
    const float* b2    = (const float*)d_in[6];
    const float* W_fc  = (const float*)d_in[7];
    const float* b_fc  = (const float*)d_in[8];
    float* out = (float*)d_out;

    cudaFuncSetAttribute(lstm2_tc4_kernel,
                         cudaFuncAttributeMaxDynamicSharedMemorySize, SMEM_BYTES);

    lstm2_tc4_kernel<<<NBLOCKS, THREADS, SMEM_BYTES>>>(
        x, W_ih1, W_hh1, b1, W_ih2, W_hh2, b2, W_fc, b_fc, out);
}

// round 14
// speedup vs baseline: 1.7817x; 1.1325x over previous
#include <cuda_runtime.h>
#include <cuda_fp16.h>
#include <cstdint>

#define H 40
#define T 256
#define BATCH 8192
#define EPB 32
#define THREADS 256
#define NBLOCKS (BATCH / EPB)   // 256

#define PITCH 88                // fp16 cols per element row (h1 0..39 | h2 40..79 | x 80..82 | pad)
#define NFRAG 160               // L1: 3kt x 20nt ; L2: 5kt x 20nt
#define OFF_BF 0
#define BF_BYTES (NFRAG * 32 * 8)           // 40960 (uint2 per lane)
#define OFF_HSHI BF_BYTES
#define HS_BYTES (2 * EPB * PITCH * 2)      // 11264 (2 buffers, hi only)
#define OFF_B1S  (OFF_HSHI + HS_BYTES)      // float[160]
#define OFF_B2S  (OFF_B1S + 640)
#define SMEM_BYTES (OFF_B2S + 640)          // 53504 -> 2 CTAs/SM

__device__ __forceinline__ float tanhfast(float x) {
    float y; asm("tanh.approx.f32 %0, %1;" : "=f"(y) : "f"(x)); return y;
}
__device__ __forceinline__ float sigf(float x) {
    return fmaf(0.5f, tanhfast(0.5f * x), 0.5f);
}
__device__ __forceinline__ uint32_t packh(__half a, __half b) {
    __half2 t; t.x = a; t.y = b;
    return *(uint32_t*)&t;
}
__device__ __forceinline__ void mma16816h(float* d, const uint32_t* a, uint32_t b0, uint32_t b1) {
    asm("mma.sync.aligned.m16n8k16.row.col.f32.f16.f16.f32 "
        "{%0,%1,%2,%3},{%4,%5,%6,%7},{%8,%9},{%0,%1,%2,%3};"
        : "+f"(d[0]), "+f"(d[1]), "+f"(d[2]), "+f"(d[3])
        : "r"(a[0]), "r"(a[1]), "r"(a[2]), "r"(a[3]), "r"(b0), "r"(b1));
}

__global__ __launch_bounds__(THREADS, 2)
void lstm2_tc5_kernel(const float* __restrict__ x,
                      const float* __restrict__ W_ih1,
                      const float* __restrict__ W_hh1,
                      const float* __restrict__ b1,
                      const float* __restrict__ W_ih2,
                      const float* __restrict__ W_hh2,
                      const float* __restrict__ b2,
                      const float* __restrict__ W_fc,
                      const float* __restrict__ b_fc,
                      float* __restrict__ out)
{
    extern __shared__ char smem[];
    uint2* __restrict__ BF = (uint2*)(smem + OFF_BF);
    __half* __restrict__ HShi = (__half*)(smem + OFF_HSHI);
    float* __restrict__ B1S = (float*)(smem + OFF_B1S);
    float* __restrict__ B2S = (float*)(smem + OFF_B2S);

    const int tid  = threadIdx.x;
    const int w    = tid >> 5;
    const int lane = tid & 31;
    const int gid  = lane >> 2;     // 0..7
    const int tig  = lane & 3;      // 0..3
    const int mt   = w >> 2;        // 0..1 : m-tile (16 elements)
    const int ng   = w & 3;         // 0..3 : n-tiles ng*5 .. ng*5+4

    const float* xp = x + ((long)blockIdx.x * EPB + (tid & 31)) * (T * 3);

    // ---------------- init: zero both HS buffers; bias tables ----------------
    for (int i = tid; i < 2 * EPB * PITCH; i += THREADS) {
        HShi[i] = __float2half(0.0f);
    }
    for (int n = tid; n < 160; n += THREADS) {
        int r = (n & 3) * H + (n >> 2);
        B1S[n] = __ldg(b1 + r);
        B2S[n] = __ldg(b2 + r);
    }
    // ---------------- init: pack B fragments (fp16) ----------------
    for (int f = w; f < NFRAG; f += 8) {
        int layer, kt, nt;
        if (f < 60) { layer = 0; kt = f / 20; nt = f % 20; }
        else        { layer = 1; kt = (f - 60) / 20; nt = (f - 60) % 20; }
        int n = nt * 8 + gid;
        int r = (n & 3) * H + (n >> 2);   // PyTorch row = gate*H + unit
        float v[4];
        #pragma unroll
        for (int q = 0; q < 4; q++) {
            int k = kt * 16 + 2 * tig + ((q >> 1) * 8) + (q & 1);
            float val;
            if (layer == 0) {
                if (k < 40)      val = W_hh1[r * H + k];
                else if (k < 43) val = W_ih1[r * 3 + (k - 40)];
                else             val = 0.0f;          // bias folded into D-init
            } else {
                if (k < 40)      val = W_ih2[r * H + k];
                else             val = W_hh2[r * H + (k - 40)];
            }
            v[q] = val;
        }
        uint2 pk;
        pk.x = packh(__float2half_rn(v[0]), __float2half_rn(v[1]));
        pk.y = packh(__float2half_rn(v[2]), __float2half_rn(v[3]));
        BF[f * 32 + lane] = pk;
    }
    __syncthreads();
    // stage x(0) -> buf0, x(1) -> buf1
    if (tid < EPB) {
        #pragma unroll
        for (int bu = 0; bu < 2; bu++) {
            #pragma unroll
            for (int c = 0; c < 3; c++) {
                HShi[bu * EPB * PITCH + tid * PITCH + 80 + c] =
                    __float2half_rn(__ldg(xp + bu * 3 + c));
            }
        }
    }
    __syncthreads();

    // ---------------- recurrent state ----------------
    float cs1[5][2], cs2[5][2];
    #pragma unroll
    for (int i = 0; i < 5; i++) {
        cs1[i][0] = cs1[i][1] = 0.0f;
        cs2[i][0] = cs2[i][1] = 0.0f;
    }

    const int e0 = mt * 16 + gid;
    const int e1 = e0 + 8;
    const int nbase = (ng * 5) * 8 + 2 * tig;

    auto epi = [&](float D[5][4], float cs[5][2], __half* Whi, int colbase) {
        #pragma unroll
        for (int ntl = 0; ntl < 5; ntl++) {
            float u0, v0, u1, v1;
            if ((tig & 1) == 0) {
                u0 = sigf(D[ntl][0]); v0 = sigf(D[ntl][1]);
                u1 = sigf(D[ntl][2]); v1 = sigf(D[ntl][3]);
            } else {
                u0 = tanhfast(D[ntl][0]); v0 = sigf(D[ntl][1]);
                u1 = tanhfast(D[ntl][2]); v1 = sigf(D[ntl][3]);
            }
            float g0 = __shfl_xor_sync(0xffffffffu, u0, 1);
            float g1 = __shfl_xor_sync(0xffffffffu, u1, 1);
            cs[ntl][0] = fmaf(v0, cs[ntl][0], u0 * g0);
            cs[ntl][1] = fmaf(v1, cs[ntl][1], u1 * g1);
            float tc0 = tanhfast(cs[ntl][0]);
            float tc1 = tanhfast(cs[ntl][1]);
            float r0 = __shfl_xor_sync(0xffffffffu, tc0, 1);
            float r1 = __shfl_xor_sync(0xffffffffu, tc1, 1);
            if (tig & 1) {
                int unit = 2 * (ng * 5 + ntl) + (tig >> 1);
                Whi[e0 * PITCH + colbase + unit] = __float2half_rn(v0 * r0);
                Whi[e1 * PITCH + colbase + unit] = __float2half_rn(v1 * r1);
            }
        }
    };

    for (int t = 0; t < T; t++) {
        const int p = t & 1;
        __half* Phi = HShi + p * EPB * PITCH;         // buf[p]: this step's writes, x(t)
        __half* Qhi = HShi + (1 - p) * EPB * PITCH;   // buf[1-p]: h1(t-1), h2(t-1)

        // global prefetch of x(t+2)
        float xr0 = 0.f, xr1 = 0.f, xr2 = 0.f;
        if (tid < EPB) {
            int tn = (t + 2 < T) ? (t + 2) : (T - 1);
            xr0 = __ldg(xp + tn * 3 + 0);
            xr1 = __ldg(xp + tn * 3 + 1);
            xr2 = __ldg(xp + tn * 3 + 2);
        }

        float D[5][4];

        // ================= P1: L1 MMA  (A = [h1(t-1) | x(t)]) =================
        #pragma unroll
        for (int ntl = 0; ntl < 5; ntl++) {
            float bb0 = B1S[nbase + ntl * 8];
            float bb1 = B1S[nbase + ntl * 8 + 1];
            D[ntl][0] = bb0; D[ntl][1] = bb1;
            D[ntl][2] = bb0; D[ntl][3] = bb1;
        }
        #pragma unroll
        for (int kt = 0; kt < 3; kt++) {
            const int c0 = (kt < 2) ? kt * 16 + 2 * tig : 32 + 2 * tig;
            const int c8 = (kt < 2) ? kt * 16 + 8 + 2 * tig : 80 + 2 * tig;
            const __half* s8hi = (kt < 2) ? Qhi : Phi;   // x(t) lives in buf[p]
            uint32_t ah[4];
            ah[0] = *(const uint32_t*)(Qhi + e0 * PITCH + c0);
            ah[1] = *(const uint32_t*)(Qhi + e1 * PITCH + c0);
            ah[2] = *(const uint32_t*)(s8hi + e0 * PITCH + c8);
            ah[3] = *(const uint32_t*)(s8hi + e1 * PITCH + c8);
            #pragma unroll
            for (int ntl = 0; ntl < 5; ntl++) {
                uint2 bb = BF[(kt * 20 + ng * 5 + ntl) * 32 + lane];
                mma16816h(D[ntl], ah, bb.x, bb.y);
            }
        }
        // epi1: write h1(t) -> buf[p] cols 0..39
        epi(D, cs1, Phi, 0);
        __syncthreads();

        // stage x(t+2) -> buf[p] cols 80..82 (x(t) readers finished pre-BAR)
        if (tid < EPB) {
            Phi[tid * PITCH + 80] = __float2half_rn(xr0);
            Phi[tid * PITCH + 81] = __float2half_rn(xr1);
            Phi[tid * PITCH + 82] = __float2half_rn(xr2);
        }

        // ================= P3: L2 MMA  (A = [h1(t) | h2(t-1)]) =================
        #pragma unroll
        for (int ntl = 0; ntl < 5; ntl++) {
            float bb0 = B2S[nbase + ntl * 8];
            float bb1 = B2S[nbase + ntl * 8 + 1];
            D[ntl][0] = bb0; D[ntl][1] = bb1;
            D[ntl][2] = bb0; D[ntl][3] = bb1;
        }
        #pragma unroll
        for (int kt = 0; kt < 5; kt++) {
            const int c0 = kt * 16 + 2 * tig;
            const int c8 = kt * 16 + 8 + 2 * tig;
            // cols < 40 = h1(t) in buf[p]; cols >= 40 = h2(t-1) in buf[1-p]
            const __half* s0hi = (kt <= 2) ? Phi : Qhi;
            const __half* s8hi = (kt < 2) ? Phi : Qhi;
            uint32_t ah[4];
            ah[0] = *(const uint32_t*)(s0hi + e0 * PITCH + c0);
            ah[1] = *(const uint32_t*)(s0hi + e1 * PITCH + c0);
            ah[2] = *(const uint32_t*)(s8hi + e0 * PITCH + c8);
            ah[3] = *(const uint32_t*)(s8hi + e1 * PITCH + c8);
            #pragma unroll
            for (int ntl = 0; ntl < 5; ntl++) {
                uint2 bb = BF[((60 + kt * 20) + ng * 5 + ntl) * 32 + lane];
                mma16816h(D[ntl], ah, bb.x, bb.y);
            }
        }
        // epi2: write h2(t) -> buf[p] cols 40..79 (next readers cross >=1 BAR)
        epi(D, cs2, Phi, 40);
    }
    __syncthreads();

    // ---------------- FC epilogue (h2(T-1) in buf[(T-1)&1] = buf1) ----------------
    if (tid < 2 * EPB) {
        int e = tid >> 1, q = tid & 1;
        const __half* Fhi = HShi + 1 * EPB * PITCH;
        float acc = __ldg(b_fc + q);
        #pragma unroll 8
        for (int u = 0; u < H; u++) {
            acc = fmaf(__half2float(Fhi[e * PITCH + 40 + u]), __ldg(W_fc + q * H + u), acc);
        }
        out[((long)blockIdx.x * EPB + e) * 2 + q] = acc;
    }
}

extern "C" void kernel_launch(void* const* d_in, const int* in_sizes, int n_in,
                              void* d_out, int out_size)
{
    const float* x     = (const float*)d_in[0];
    const float* W_ih1 = (const float*)d_in[1];
    const float* W_hh1 = (const float*)d_in[2];
    const float* b1    = (const float*)d_in[3];
    const float* W_ih2 = (const float*)d_in[4];
    const float* W_hh2 = (const float*)d_in[5];
    const float* b2    = (const float*)d_in[6];
    const float* W_fc  = (const float*)d_in[7];
    const float* b_fc  = (const float*)d_in[8];
    float* out = (float*)d_out;

    cudaFuncSetAttribute(lstm2_tc5_kernel,
                         cudaFuncAttributeMaxDynamicSharedMemorySize, SMEM_BYTES);

    lstm2_tc5_kernel<<<NBLOCKS, THREADS, SMEM_BYTES>>>(
        x, W_ih1, W_hh1, b1, W_ih2, W_hh2, b2, W_fc, b_fc, out);
}